// round 13
// baseline (speedup 1.0000x reference)
#include <cuda_runtime.h>
#include <cuda_bf16.h>
#include <math.h>
#include <stdint.h>

#define NA   50000
#define NS   5000
#define EAA  500000
#define EAS  250000
#define C    128
#define ED   8

#define SCAN_ELEMS 2048
#define NB_AA ((NA + SCAN_ELEMS - 1) / SCAN_ELEMS)
#define NB_AS ((NS + SCAN_ELEMS - 1) / SCAN_ELEMS)

// ---------------- device scratch ----------------
__device__ float g_ha[NA * C];
__device__ float g_hs[NS * C];
__device__ float g_xl_aa[NA * C];
__device__ float g_xr_aa[NA * C];
__device__ float g_xl_as[NA * C];
__device__ float g_xr_as[NS * C];
__device__ int  g_cnt_aa[NA];
__device__ int  g_off_aa[NA + 4];
__device__ int2 g_csr_aa[EAA];
__device__ int  g_cnt_as[NS];
__device__ int  g_off_as[NS + 4];
__device__ int2 g_csr_as[EAS];
__device__ int  g_bsum_aa[NB_AA + 1];
__device__ int  g_bsum_as[NB_AS + 1];
__device__ int  g_wctrA[3];
__device__ int  g_wctrS[3];

// ---------------- helpers ----------------
__device__ __forceinline__ float lkrelu(float x) { return x > 0.0f ? x : 0.2f * x; }

__device__ __forceinline__ uint32_t bf16_hi_bits(float v, float& hf) {
    __nv_bfloat16 h = __float2bfloat16(v);
    hf = __bfloat162float(h);
    uint16_t b = *(uint16_t*)&h;
    return (uint32_t)b;
}

__device__ __forceinline__ void mma16(float* c, const uint32_t* a, const uint32_t* b) {
    asm volatile(
        "mma.sync.aligned.m16n8k16.row.col.f32.bf16.bf16.f32 "
        "{%0,%1,%2,%3}, {%4,%5,%6,%7}, {%8,%9}, {%0,%1,%2,%3};"
        : "+f"(c[0]), "+f"(c[1]), "+f"(c[2]), "+f"(c[3])
        : "r"(a[0]), "r"(a[1]), "r"(a[2]), "r"(a[3]),
          "r"(b[0]), "r"(b[1]));
}

// ---------------- BF16 GEMM: 1024 threads, m16n32 warp tile, 3xBF16 ----------------
#define SM_GEMM_BYTES (65536 + 67584)

__global__ __launch_bounds__(1024, 1) void gemm_dual(
    const float* __restrict__ XA,
    const float* __restrict__ Wa0, const float* __restrict__ Wa1, const float* __restrict__ Wa2,
    float* __restrict__ Ya0, float* __restrict__ Ya1, float* __restrict__ Ya2,
    int NrowsA, int kshiftA, int gridA,
    const float* __restrict__ XS, const float* __restrict__ Ws,
    float* __restrict__ Ys, int NrowsS, int kshiftS)
{
    extern __shared__ char smc[];

    const float *X, *W0, *W1, *W2;
    float *Y0, *Y1, *Y2;
    int Nrows, kshift, nW, rbase;
    if ((int)blockIdx.x < gridA) {
        X = XA; W0 = Wa0; W1 = Wa1; W2 = Wa2; Y0 = Ya0; Y1 = Ya1; Y2 = Ya2;
        Nrows = NrowsA; kshift = kshiftA; nW = 3; rbase = blockIdx.x * 128;
    } else {
        X = XS; W0 = Ws; W1 = Ws; W2 = Ws; Y0 = Ys; Y1 = Ys; Y2 = Ys;
        Nrows = NrowsS; kshift = kshiftS; nW = 1; rbase = (blockIdx.x - gridA) * 128;
    }

    const int K = 1 << kshift;
    const int ksteps = K >> 4;
    uint32_t* sAhi = (uint32_t*)smc;                  // 128*K/2 u32 (bf16 pairs)
    uint32_t* sAlo = sAhi + 64 * K;
    uint32_t* sWhi = (uint32_t*)(smc + 128 * K * 4);
    uint32_t* sWlo = sWhi + ksteps * 4 * 132 * 2;

    const int tid = threadIdx.x;
    const int lane = tid & 31;
    const int warp = tid >> 5;
    const int gid = lane >> 2;
    const int tg  = lane & 3;
    const int wm = warp >> 2;
    const int wn = warp & 3;

    // ---- stage A hi/lo bf16 pairs (u32 stores, float2 loads) ----
    {
        const int total2 = 64 << kshift;          // pairs
        const int kpmask = (K >> 1) - 1;
        const int kps = kshift - 1;
        for (int idx = tid; idx < total2; idx += 1024) {
            int row = idx >> kps, kp = idx & kpmask;
            int k = kp << 1;
            float2 v = make_float2(0.f, 0.f);
            if (rbase + row < Nrows)
                v = *(const float2*)&X[((size_t)(rbase + row) << kshift) + k];
            float h0f, h1f;
            uint32_t h0 = bf16_hi_bits(v.x, h0f);
            uint32_t h1 = bf16_hi_bits(v.y, h1f);
            float l0f, l1f;
            uint32_t l0 = bf16_hi_bits(v.x - h0f, l0f);
            uint32_t l1 = bf16_hi_bits(v.y - h1f, l1f);
            int frag = (row >> 4) * ksteps + (k >> 4);
            int alane = (row & 7) * 4 + ((k >> 1) & 3);
            int reg = ((row >> 3) & 1) + 2 * ((k >> 3) & 1);
            int u32i = frag * 128 + alane * 4 + reg;
            sAhi[u32i] = h0 | (h1 << 16);
            sAlo[u32i] = l0 | (l1 << 16);
        }
    }
    __syncthreads();

    const uint4* A4hi = (const uint4*)sAhi;
    const uint4* A4lo = (const uint4*)sAlo;
    const uint2* Whi2 = (const uint2*)sWhi;
    const uint2* Wlo2 = (const uint2*)sWlo;

    for (int wi = 0; wi < nW; wi++) {
        const float* W = (wi == 0) ? W0 : (wi == 1) ? W1 : W2;

        // ---- stage W hi/lo bf16 pairs (u32 stores) ----
        {
            const int total2 = K << 6;            // (K/2)*128 pairs
            for (int idx = tid; idx < total2; idx += 1024) {
                int kp = idx >> 7, n = idx & 127;
                int k = kp << 1;
                float v0 = W[((size_t)k << 7) + n];
                float v1 = W[((size_t)(k + 1) << 7) + n];
                float h0f, h1f;
                uint32_t h0 = bf16_hi_bits(v0, h0f);
                uint32_t h1 = bf16_hi_bits(v1, h1f);
                float l0f, l1f;
                uint32_t l0 = bf16_hi_bits(v0 - h0f, l0f);
                uint32_t l1 = bf16_hi_bits(v1 - h1f, l1f);
                int u32i = (((k >> 4) * 4 + ((k >> 1) & 3)) * 132 + n) * 2
                           + ((k >> 3) & 1);
                sWhi[u32i] = h0 | (h1 << 16);
                sWlo[u32i] = l0 | (l1 << 16);
            }
        }
        __syncthreads();

        float acc[4][4];
#pragma unroll
        for (int in = 0; in < 4; in++)
#pragma unroll
            for (int j = 0; j < 4; j++) acc[in][j] = 0.0f;

        for (int ks = 0; ks < ksteps; ks++) {
            const int wb = (ks * 4 + tg) * 132 + wn * 32 + gid;
            uint2 bhi[4], blo[4];
#pragma unroll
            for (int in = 0; in < 4; in++) {
                bhi[in] = Whi2[wb + in * 8];
                blo[in] = Wlo2[wb + in * 8];
            }
            const int fidx = (wm * ksteps + ks) * 32 + lane;
            uint4 ah = A4hi[fidx];
            uint4 al = A4lo[fidx];
#pragma unroll
            for (int in = 0; in < 4; in++)
                mma16(acc[in], &ah.x, &bhi[in].x);
#pragma unroll
            for (int in = 0; in < 4; in++)
                mma16(acc[in], &al.x, &bhi[in].x);
#pragma unroll
            for (int in = 0; in < 4; in++)
                mma16(acc[in], &ah.x, &blo[in].x);
        }

        float* Y = (wi == 0) ? Y0 : (wi == 1) ? Y1 : Y2;
        {
            int r0 = rbase + wm * 16 + gid;
#pragma unroll
            for (int in = 0; in < 4; in++) {
                int col = wn * 32 + in * 8 + tg * 2;
                if (r0 < Nrows)
                    *(float2*)&Y[((size_t)r0 << 7) + col] =
                        make_float2(acc[in][0], acc[in][1]);
                if (r0 + 8 < Nrows)
                    *(float2*)&Y[((size_t)(r0 + 8) << 7) + col] =
                        make_float2(acc[in][2], acc[in][3]);
            }
        }
        __syncthreads();
    }
}

// ---------------- CSR build ----------------
__global__ void zero_cnt()
{
    int i = blockIdx.x * 256 + threadIdx.x;
    if (i < NA) g_cnt_aa[i] = 0;
    if (i < NS) g_cnt_as[i] = 0;
    if (i < 3) { g_wctrA[i] = 0; g_wctrS[i] = 0; }
}

__global__ void hist2(const int* __restrict__ dst_aa, const int* __restrict__ dst_as)
{
    int e = blockIdx.x * 256 + threadIdx.x;
    if (e < EAA) atomicAdd(&g_cnt_aa[dst_aa[e]], 1);
    if (e < EAS) atomicAdd(&g_cnt_as[dst_as[e]], 1);
}

__global__ __launch_bounds__(512) void scan1(int NBa)
{
    __shared__ int ws[16];
    const int b = blockIdx.x;
    const int* cnt = (b < NBa) ? g_cnt_aa : g_cnt_as;
    int* bsum      = (b < NBa) ? g_bsum_aa : g_bsum_as;
    const int lb   = (b < NBa) ? b : b - NBa;
    const int N    = (b < NBa) ? NA : NS;

    const int t = threadIdx.x;
    const int base = lb * SCAN_ELEMS + t * 4;
    int4 v = make_int4(0, 0, 0, 0);
    if (base + 3 < N) v = *(const int4*)(cnt + base);
    else {
        if (base + 0 < N) v.x = cnt[base + 0];
        if (base + 1 < N) v.y = cnt[base + 1];
        if (base + 2 < N) v.z = cnt[base + 2];
    }
    int s = v.x + v.y + v.z + v.w;
#pragma unroll
    for (int o = 16; o; o >>= 1) s += __shfl_xor_sync(0xffffffffu, s, o);
    if ((t & 31) == 0) ws[t >> 5] = s;
    __syncthreads();
    if (t < 32) {
        int x = (t < 16) ? ws[t] : 0;
#pragma unroll
        for (int o = 16; o; o >>= 1) x += __shfl_xor_sync(0xffffffffu, x, o);
        if (t == 0) bsum[lb] = x;
    }
}

__global__ void scan2()
{
    if (threadIdx.x != 0) return;
    if (blockIdx.x == 0) {
        int run = 0;
        for (int i = 0; i < NB_AA; i++) { int t = g_bsum_aa[i]; g_bsum_aa[i] = run; run += t; }
        g_bsum_aa[NB_AA] = run;
    } else {
        int run = 0;
        for (int i = 0; i < NB_AS; i++) { int t = g_bsum_as[i]; g_bsum_as[i] = run; run += t; }
        g_bsum_as[NB_AS] = run;
    }
}

__global__ __launch_bounds__(512) void scan3(int NBa)
{
    __shared__ int ws[16];
    const int b = blockIdx.x;
    int* cnt        = (b < NBa) ? g_cnt_aa : g_cnt_as;
    int* off        = (b < NBa) ? g_off_aa : g_off_as;
    const int* bsum = (b < NBa) ? g_bsum_aa : g_bsum_as;
    const int lb    = (b < NBa) ? b : b - NBa;
    const int N     = (b < NBa) ? NA : NS;
    const int NB    = (b < NBa) ? NB_AA : NB_AS;

    const int t = threadIdx.x;
    const int wid = t >> 5, lane = t & 31;
    const int base = lb * SCAN_ELEMS + t * 4;
    int4 v = make_int4(0, 0, 0, 0);
    if (base + 3 < N) v = *(const int4*)(cnt + base);
    else {
        if (base + 0 < N) v.x = cnt[base + 0];
        if (base + 1 < N) v.y = cnt[base + 1];
        if (base + 2 < N) v.z = cnt[base + 2];
    }
    int s = v.x + v.y + v.z + v.w;
    int inc = s;
#pragma unroll
    for (int o = 1; o < 32; o <<= 1) {
        int u = __shfl_up_sync(0xffffffffu, inc, o);
        if (lane >= o) inc += u;
    }
    if (lane == 31) ws[wid] = inc;
    __syncthreads();
    if (t < 32) {
        int x = (t < 16) ? ws[t] : 0;
#pragma unroll
        for (int o = 1; o < 32; o <<= 1) {
            int u = __shfl_up_sync(0xffffffffu, x, o);
            if (t >= o) x += u;
        }
        if (t < 16) ws[t] = x;
    }
    __syncthreads();
    int wbase = (wid == 0) ? 0 : ws[wid - 1];
    int tbase = bsum[lb] + wbase + (inc - s);
    int4 p = make_int4(tbase, tbase + v.x, tbase + v.x + v.y, tbase + v.x + v.y + v.z);
    if (base + 3 < N) {
        *(int4*)(off + base) = p;
        *(int4*)(cnt + base) = make_int4(0, 0, 0, 0);
    } else {
        if (base + 0 < N) { off[base + 0] = p.x; cnt[base + 0] = 0; }
        if (base + 1 < N) { off[base + 1] = p.y; cnt[base + 1] = 0; }
        if (base + 2 < N) { off[base + 2] = p.z; cnt[base + 2] = 0; }
    }
    if (lb == 0 && t == 0) off[N] = bsum[NB];
}

__global__ void csr_fill2(const int* __restrict__ dst_aa, const int* __restrict__ src_aa,
                          const int* __restrict__ dst_as, const int* __restrict__ src_as)
{
    int e = blockIdx.x * 256 + threadIdx.x;
    if (e < EAA) {
        int d = dst_aa[e];
        int pos = g_off_aa[d] + atomicAdd(&g_cnt_aa[d], 1);
        g_csr_aa[pos] = make_int2(e, src_aa[e]);
    }
    if (e < EAS) {
        int d = dst_as[e];
        int pos = g_off_as[d] + atomicAdd(&g_cnt_as[d], 1);
        g_csr_as[pos] = make_int2(e, src_as[e]);
    }
}

// ---------------- per-dst GATv2 aggregation (regs, predicated batches) ----------------
__device__ __forceinline__ void process_dst(
    int d, const int2* __restrict__ csr, const int* __restrict__ off,
    const float* __restrict__ eattr, const float4* Wreg,
    float4 a4, float4 bv,
    const float4* __restrict__ xl4, const float* __restrict__ xr,
    float* __restrict__ out, int relu, int lane)
{
    const float4 xrv = ((const float4*)xr)[(size_t)d * 32 + lane];
    float4 acc = make_float4(0.f, 0.f, 0.f, 0.f);
    float den = 0.0f;

    const int beg = off[d], end = off[d + 1];
    for (int i = beg; i < end; i += 4) {
        int2 es[4];
        float4 x[4], eaAv[4], eaBv[4];
#pragma unroll
        for (int j = 0; j < 4; j++) es[j] = csr[min(i + j, end - 1)];
#pragma unroll
        for (int j = 0; j < 4; j++) x[j] = xl4[(size_t)es[j].y * 32 + lane];
#pragma unroll
        for (int j = 0; j < 4; j++) {
            const float4* ea = (const float4*)(eattr + (size_t)es[j].x * ED);
            eaAv[j] = ea[0]; eaBv[j] = ea[1];
        }
        float lg[4];
#pragma unroll
        for (int j = 0; j < 4; j++) {
            float4 m = make_float4(x[j].x + xrv.x, x[j].y + xrv.y,
                                   x[j].z + xrv.z, x[j].w + xrv.w);
            float ja[ED] = {eaAv[j].x, eaAv[j].y, eaAv[j].z, eaAv[j].w,
                            eaBv[j].x, eaBv[j].y, eaBv[j].z, eaBv[j].w};
#pragma unroll
            for (int q = 0; q < ED; q++) {
                float4 wv = Wreg[q];
                m.x = fmaf(ja[q], wv.x, m.x); m.y = fmaf(ja[q], wv.y, m.y);
                m.z = fmaf(ja[q], wv.z, m.z); m.w = fmaf(ja[q], wv.w, m.w);
            }
            lg[j] = lkrelu(m.x) * a4.x + lkrelu(m.y) * a4.y +
                    lkrelu(m.z) * a4.z + lkrelu(m.w) * a4.w;
        }
#pragma unroll
        for (int o = 16; o; o >>= 1) {
#pragma unroll
            for (int j = 0; j < 4; j++)
                lg[j] += __shfl_xor_sync(0xffffffffu, lg[j], o);
        }
#pragma unroll
        for (int j = 0; j < 4; j++) {
            const float ee = (i + j < end) ? __expf(lg[j]) : 0.0f;
            den += ee;
            acc.x = fmaf(ee, x[j].x, acc.x); acc.y = fmaf(ee, x[j].y, acc.y);
            acc.z = fmaf(ee, x[j].z, acc.z); acc.w = fmaf(ee, x[j].w, acc.w);
        }
    }

    const float inv = 1.0f / fmaxf(den, 1e-16f);
    float4 v = make_float4(acc.x * inv + bv.x, acc.y * inv + bv.y,
                           acc.z * inv + bv.z, acc.w * inv + bv.w);
    if (relu) {
        v.x = fmaxf(v.x, 0.f); v.y = fmaxf(v.y, 0.f);
        v.z = fmaxf(v.z, 0.f); v.w = fmaxf(v.w, 0.f);
    }
    float sq = v.x * v.x + v.y * v.y + v.z * v.z + v.w * v.w;
#pragma unroll
    for (int o = 16; o; o >>= 1) sq += __shfl_xor_sync(0xffffffffu, sq, o);
    const float s = 1.0f / fmaxf(sqrtf(sq), 1e-12f);
    ((float4*)out)[(size_t)d * 32 + lane] =
        make_float4(v.x * s, v.y * s, v.z * s, v.w * s);
}

// ---------------- persistent work-stealing aggregation ----------------
__global__ __launch_bounds__(256) void gat_persist(
    const float* __restrict__ eaA, const float* __restrict__ WeA,
    const float* __restrict__ attA, const float* __restrict__ xlA,
    const float* __restrict__ xrA, const float* __restrict__ bA,
    float* __restrict__ outA,
    const float* __restrict__ eaS, const float* __restrict__ WeS,
    const float* __restrict__ attS, const float* __restrict__ xlS,
    const float* __restrict__ xrS, const float* __restrict__ bS,
    float* __restrict__ outS,
    int relu, int* __restrict__ ctrA, int* __restrict__ ctrS)
{
    const int lane = threadIdx.x & 31;
    float4 Wreg[ED];

    // ---- style phase (degree ~50, long tasks first) ----
    {
#pragma unroll
        for (int q = 0; q < ED; q++) Wreg[q] = ((const float4*)WeS)[q * 32 + lane];
        const float4 a4 = ((const float4*)attS)[lane];
        const float4 bv = ((const float4*)bS)[lane];
        for (;;) {
            int i = 0;
            if (lane == 0) i = atomicAdd(ctrS, 2);
            i = __shfl_sync(0xffffffffu, i, 0);
            if (i >= NS) break;
            const int e = min(i + 2, NS);
            for (int d = i; d < e; d++)
                process_dst(d, g_csr_as, g_off_as, eaS, Wreg, a4, bv,
                            (const float4*)xlS, xrS, outS, relu, lane);
        }
    }
    // ---- artist phase (degree ~10) ----
    {
#pragma unroll
        for (int q = 0; q < ED; q++) Wreg[q] = ((const float4*)WeA)[q * 32 + lane];
        const float4 a4 = ((const float4*)attA)[lane];
        const float4 bv = ((const float4*)bA)[lane];
        for (;;) {
            int i = 0;
            if (lane == 0) i = atomicAdd(ctrA, 8);
            i = __shfl_sync(0xffffffffu, i, 0);
            if (i >= NA) break;
            const int e = min(i + 8, NA);
            for (int d = i; d < e; d++)
                process_dst(d, g_csr_aa, g_off_aa, eaA, Wreg, a4, bv,
                            (const float4*)xlA, xrA, outA, relu, lane);
        }
    }
}

// ---------------- host ----------------
extern "C" void kernel_launch(void* const* d_in, const int* in_sizes, int n_in,
                              void* d_out, int out_size)
{
    const float* x_a   = (const float*)d_in[0];
    const float* x_s   = (const float*)d_in[1];
    const int* src_aa  = (const int*)d_in[2];
    const int* dst_aa  = (const int*)d_in[3];
    const float* ea_aa = (const float*)d_in[4];
    const int* src_as  = (const int*)d_in[5];
    const int* dst_as  = (const int*)d_in[6];
    const float* ea_as = (const float*)d_in[7];

    const float* Wl0_aa  = (const float*)d_in[8];
    const float* Wr0_aa  = (const float*)d_in[9];
    const float* att0_aa = (const float*)d_in[10];
    const float* We0_aa  = (const float*)d_in[11];
    const float* b0_aa   = (const float*)d_in[12];
    const float* Wl0_as  = (const float*)d_in[13];
    const float* Wr0_as  = (const float*)d_in[14];
    const float* att0_as = (const float*)d_in[15];
    const float* We0_as  = (const float*)d_in[16];
    const float* b0_as   = (const float*)d_in[17];
    const float* Wl_aa   = (const float*)d_in[18];
    const float* Wr_aa   = (const float*)d_in[19];
    const float* att_aa  = (const float*)d_in[20];
    const float* We_aa   = (const float*)d_in[21];
    const float* b_aa    = (const float*)d_in[22];
    const float* Wl_as   = (const float*)d_in[23];
    const float* Wr_as   = (const float*)d_in[24];
    const float* att_as  = (const float*)d_in[25];
    const float* We_as   = (const float*)d_in[26];
    const float* b_as    = (const float*)d_in[27];

    float *ha, *hs, *xl_aa, *xr_aa, *xl_as, *xr_as;
    int *wctrA, *wctrS;
    cudaGetSymbolAddress((void**)&ha,    g_ha);
    cudaGetSymbolAddress((void**)&hs,    g_hs);
    cudaGetSymbolAddress((void**)&xl_aa, g_xl_aa);
    cudaGetSymbolAddress((void**)&xr_aa, g_xr_aa);
    cudaGetSymbolAddress((void**)&xl_as, g_xl_as);
    cudaGetSymbolAddress((void**)&xr_as, g_xr_as);
    cudaGetSymbolAddress((void**)&wctrA, g_wctrA);
    cudaGetSymbolAddress((void**)&wctrS, g_wctrS);

    cudaFuncSetAttribute(gemm_dual, cudaFuncAttributeMaxDynamicSharedMemorySize, SM_GEMM_BYTES);

    const int GA = (NA + 127) / 128;    // 391
    const int GS = (NS + 127) / 128;    // 40
    const int PERSIST_BLOCKS = 608;

    zero_cnt<<<(NA + 255) / 256, 256>>>();                                 // 0
    hist2<<<(EAA + 255) / 256, 256>>>(dst_aa, dst_as);                     // 1
    scan1<<<NB_AA + NB_AS, 512>>>(NB_AA);                                  // 2
    gemm_dual<<<GA + GS, 1024, SM_GEMM_BYTES>>>(                           // 3
        x_a, Wl0_aa, Wr0_aa, Wl0_as, xl_aa, xr_aa, xl_as, NA, 7, GA,
        x_s, Wr0_as, xr_as, NS, 6);
    scan2<<<2, 32>>>();                                                    // 4
    scan3<<<NB_AA + NB_AS, 512>>>(NB_AA);                                  // 5
    csr_fill2<<<(EAA + 255) / 256, 256>>>(dst_aa, src_aa, dst_as, src_as); // 6

    for (int layer = 0; layer < 3; layer++) {
        const float *patt_aa, *pWe_aa, *pb_aa, *patt_as, *pWe_as, *pb_as;
        if (layer > 0) {
            int j = layer - 1;
            const float* pWl_aa = Wl_aa + (size_t)j * C * C;
            const float* pWr_aa = Wr_aa + (size_t)j * C * C;
            const float* pWl_as = Wl_as + (size_t)j * C * C;
            const float* pWr_as = Wr_as + (size_t)j * C * C;
            gemm_dual<<<GA + GS, 1024, SM_GEMM_BYTES>>>(
                ha, pWl_aa, pWr_aa, pWl_as, xl_aa, xr_aa, xl_as, NA, 7, GA,
                hs, pWr_as, xr_as, NS, 7);
            patt_aa = att_aa + (size_t)j * C;  pWe_aa = We_aa + (size_t)j * ED * C;
            pb_aa = b_aa + (size_t)j * C;
            patt_as = att_as + (size_t)j * C;  pWe_as = We_as + (size_t)j * ED * C;
            pb_as = b_as + (size_t)j * C;
        } else {
            patt_aa = att0_aa; pWe_aa = We0_aa; pb_aa = b0_aa;
            patt_as = att0_as; pWe_as = We0_as; pb_as = b0_as;
        }

        int relu = (layer < 2) ? 1 : 0;
        float* outA = (layer == 2) ? (float*)d_out : ha;
        float* outS = (layer == 2) ? ((float*)d_out + (size_t)NA * C) : hs;

        gat_persist<<<PERSIST_BLOCKS, 256>>>(
            ea_aa, pWe_aa, patt_aa, xl_aa, xr_aa, pb_aa, outA,
            ea_as, pWe_as, patt_as, xl_as, xr_as, pb_as, outS,
            relu, wctrA + layer, wctrS + layer);
    }
}

// round 14
// speedup vs baseline: 1.1920x; 1.1920x over previous
#include <cuda_runtime.h>
#include <cuda_bf16.h>
#include <math.h>
#include <stdint.h>

#define NA   50000
#define NS   5000
#define EAA  500000
#define EAS  250000
#define C    128
#define ED   8

#define SCAN_ELEMS 2048
#define NB_AA ((NA + SCAN_ELEMS - 1) / SCAN_ELEMS)
#define NB_AS ((NS + SCAN_ELEMS - 1) / SCAN_ELEMS)

// ---------------- device scratch ----------------
__device__ float g_ha[NA * C];
__device__ float g_hs[NS * C];
__device__ float g_xl_aa[NA * C];
__device__ float g_xr_aa[NA * C];
__device__ float g_xl_as[NA * C];
__device__ float g_xr_as[NS * C];
__device__ int  g_cnt_aa[NA];
__device__ int  g_off_aa[NA + 4];
__device__ int2 g_csr_aa[EAA];
__device__ int  g_cnt_as[NS];
__device__ int  g_off_as[NS + 4];
__device__ int2 g_csr_as[EAS];
__device__ int  g_bsum_aa[NB_AA + 1];
__device__ int  g_bsum_as[NB_AS + 1];
__device__ int  g_wctrA[3];
__device__ int  g_wctrS[3];

// ---------------- helpers ----------------
__device__ __forceinline__ float lkrelu(float x) { return x > 0.0f ? x : 0.2f * x; }

__device__ __forceinline__ uint32_t bf16_hi_bits(float v, float& hf) {
    __nv_bfloat16 h = __float2bfloat16(v);
    hf = __bfloat162float(h);
    uint16_t b = *(uint16_t*)&h;
    return (uint32_t)b;
}

__device__ __forceinline__ void mma16(float* c, const uint32_t* a, const uint32_t* b) {
    asm volatile(
        "mma.sync.aligned.m16n8k16.row.col.f32.bf16.bf16.f32 "
        "{%0,%1,%2,%3}, {%4,%5,%6,%7}, {%8,%9}, {%0,%1,%2,%3};"
        : "+f"(c[0]), "+f"(c[1]), "+f"(c[2]), "+f"(c[3])
        : "r"(a[0]), "r"(a[1]), "r"(a[2]), "r"(a[3]),
          "r"(b[0]), "r"(b[1]));
}

// ---------------- BF16 GEMM: 1024 threads, m16n32 warp tile, 3xBF16 ----------------
#define SM_GEMM_BYTES (65536 + 67584)

__global__ __launch_bounds__(1024, 1) void gemm_dual(
    const float* __restrict__ XA,
    const float* __restrict__ Wa0, const float* __restrict__ Wa1, const float* __restrict__ Wa2,
    float* __restrict__ Ya0, float* __restrict__ Ya1, float* __restrict__ Ya2,
    int NrowsA, int kshiftA, int gridA,
    const float* __restrict__ XS, const float* __restrict__ Ws,
    float* __restrict__ Ys, int NrowsS, int kshiftS)
{
    extern __shared__ char smc[];

    const float *X, *W0, *W1, *W2;
    float *Y0, *Y1, *Y2;
    int Nrows, kshift, nW, rbase;
    if ((int)blockIdx.x < gridA) {
        X = XA; W0 = Wa0; W1 = Wa1; W2 = Wa2; Y0 = Ya0; Y1 = Ya1; Y2 = Ya2;
        Nrows = NrowsA; kshift = kshiftA; nW = 3; rbase = blockIdx.x * 128;
    } else {
        X = XS; W0 = Ws; W1 = Ws; W2 = Ws; Y0 = Ys; Y1 = Ys; Y2 = Ys;
        Nrows = NrowsS; kshift = kshiftS; nW = 1; rbase = (blockIdx.x - gridA) * 128;
    }

    const int K = 1 << kshift;
    const int ksteps = K >> 4;
    uint32_t* sAhi = (uint32_t*)smc;                  // 128*K/2 u32 (bf16 pairs)
    uint32_t* sAlo = sAhi + 64 * K;
    uint32_t* sWhi = (uint32_t*)(smc + 128 * K * 4);
    uint32_t* sWlo = sWhi + ksteps * 4 * 132 * 2;

    const int tid = threadIdx.x;
    const int lane = tid & 31;
    const int warp = tid >> 5;
    const int gid = lane >> 2;
    const int tg  = lane & 3;
    const int wm = warp >> 2;
    const int wn = warp & 3;

    // ---- stage A hi/lo bf16 pairs (u32 stores, float2 loads) ----
    {
        const int total2 = 64 << kshift;
        const int kpmask = (K >> 1) - 1;
        const int kps = kshift - 1;
        for (int idx = tid; idx < total2; idx += 1024) {
            int row = idx >> kps, kp = idx & kpmask;
            int k = kp << 1;
            float2 v = make_float2(0.f, 0.f);
            if (rbase + row < Nrows)
                v = *(const float2*)&X[((size_t)(rbase + row) << kshift) + k];
            float h0f, h1f;
            uint32_t h0 = bf16_hi_bits(v.x, h0f);
            uint32_t h1 = bf16_hi_bits(v.y, h1f);
            float l0f, l1f;
            uint32_t l0 = bf16_hi_bits(v.x - h0f, l0f);
            uint32_t l1 = bf16_hi_bits(v.y - h1f, l1f);
            int frag = (row >> 4) * ksteps + (k >> 4);
            int alane = (row & 7) * 4 + ((k >> 1) & 3);
            int reg = ((row >> 3) & 1) + 2 * ((k >> 3) & 1);
            int u32i = frag * 128 + alane * 4 + reg;
            sAhi[u32i] = h0 | (h1 << 16);
            sAlo[u32i] = l0 | (l1 << 16);
        }
    }
    __syncthreads();

    const uint4* A4hi = (const uint4*)sAhi;
    const uint4* A4lo = (const uint4*)sAlo;
    const uint2* Whi2 = (const uint2*)sWhi;
    const uint2* Wlo2 = (const uint2*)sWlo;

    for (int wi = 0; wi < nW; wi++) {
        const float* W = (wi == 0) ? W0 : (wi == 1) ? W1 : W2;

        {
            const int total2 = K << 6;
            for (int idx = tid; idx < total2; idx += 1024) {
                int kp = idx >> 7, n = idx & 127;
                int k = kp << 1;
                float v0 = W[((size_t)k << 7) + n];
                float v1 = W[((size_t)(k + 1) << 7) + n];
                float h0f, h1f;
                uint32_t h0 = bf16_hi_bits(v0, h0f);
                uint32_t h1 = bf16_hi_bits(v1, h1f);
                float l0f, l1f;
                uint32_t l0 = bf16_hi_bits(v0 - h0f, l0f);
                uint32_t l1 = bf16_hi_bits(v1 - h1f, l1f);
                int u32i = (((k >> 4) * 4 + ((k >> 1) & 3)) * 132 + n) * 2
                           + ((k >> 3) & 1);
                sWhi[u32i] = h0 | (h1 << 16);
                sWlo[u32i] = l0 | (l1 << 16);
            }
        }
        __syncthreads();

        float acc[4][4];
#pragma unroll
        for (int in = 0; in < 4; in++)
#pragma unroll
            for (int j = 0; j < 4; j++) acc[in][j] = 0.0f;

        for (int ks = 0; ks < ksteps; ks++) {
            const int wb = (ks * 4 + tg) * 132 + wn * 32 + gid;
            uint2 bhi[4], blo[4];
#pragma unroll
            for (int in = 0; in < 4; in++) {
                bhi[in] = Whi2[wb + in * 8];
                blo[in] = Wlo2[wb + in * 8];
            }
            const int fidx = (wm * ksteps + ks) * 32 + lane;
            uint4 ah = A4hi[fidx];
            uint4 al = A4lo[fidx];
#pragma unroll
            for (int in = 0; in < 4; in++)
                mma16(acc[in], &ah.x, &bhi[in].x);
#pragma unroll
            for (int in = 0; in < 4; in++)
                mma16(acc[in], &al.x, &bhi[in].x);
#pragma unroll
            for (int in = 0; in < 4; in++)
                mma16(acc[in], &ah.x, &blo[in].x);
        }

        float* Y = (wi == 0) ? Y0 : (wi == 1) ? Y1 : Y2;
        {
            int r0 = rbase + wm * 16 + gid;
#pragma unroll
            for (int in = 0; in < 4; in++) {
                int col = wn * 32 + in * 8 + tg * 2;
                if (r0 < Nrows)
                    *(float2*)&Y[((size_t)r0 << 7) + col] =
                        make_float2(acc[in][0], acc[in][1]);
                if (r0 + 8 < Nrows)
                    *(float2*)&Y[((size_t)(r0 + 8) << 7) + col] =
                        make_float2(acc[in][2], acc[in][3]);
            }
        }
        __syncthreads();
    }
}

// ---------------- CSR build ----------------
__global__ void zero_cnt()
{
    int i = blockIdx.x * 256 + threadIdx.x;
    if (i < NA) g_cnt_aa[i] = 0;
    if (i < NS) g_cnt_as[i] = 0;
    if (i < 3) { g_wctrA[i] = 0; g_wctrS[i] = 0; }
}

__global__ void hist2(const int* __restrict__ dst_aa, const int* __restrict__ dst_as)
{
    int e = blockIdx.x * 256 + threadIdx.x;
    if (e < EAA) atomicAdd(&g_cnt_aa[dst_aa[e]], 1);
    if (e < EAS) atomicAdd(&g_cnt_as[dst_as[e]], 1);
}

__global__ __launch_bounds__(512) void scan1(int NBa)
{
    __shared__ int ws[16];
    const int b = blockIdx.x;
    const int* cnt = (b < NBa) ? g_cnt_aa : g_cnt_as;
    int* bsum      = (b < NBa) ? g_bsum_aa : g_bsum_as;
    const int lb   = (b < NBa) ? b : b - NBa;
    const int N    = (b < NBa) ? NA : NS;

    const int t = threadIdx.x;
    const int base = lb * SCAN_ELEMS + t * 4;
    int4 v = make_int4(0, 0, 0, 0);
    if (base + 3 < N) v = *(const int4*)(cnt + base);
    else {
        if (base + 0 < N) v.x = cnt[base + 0];
        if (base + 1 < N) v.y = cnt[base + 1];
        if (base + 2 < N) v.z = cnt[base + 2];
    }
    int s = v.x + v.y + v.z + v.w;
#pragma unroll
    for (int o = 16; o; o >>= 1) s += __shfl_xor_sync(0xffffffffu, s, o);
    if ((t & 31) == 0) ws[t >> 5] = s;
    __syncthreads();
    if (t < 32) {
        int x = (t < 16) ? ws[t] : 0;
#pragma unroll
        for (int o = 16; o; o >>= 1) x += __shfl_xor_sync(0xffffffffu, x, o);
        if (t == 0) bsum[lb] = x;
    }
}

__global__ void scan2()
{
    if (threadIdx.x != 0) return;
    if (blockIdx.x == 0) {
        int run = 0;
        for (int i = 0; i < NB_AA; i++) { int t = g_bsum_aa[i]; g_bsum_aa[i] = run; run += t; }
        g_bsum_aa[NB_AA] = run;
    } else {
        int run = 0;
        for (int i = 0; i < NB_AS; i++) { int t = g_bsum_as[i]; g_bsum_as[i] = run; run += t; }
        g_bsum_as[NB_AS] = run;
    }
}

__global__ __launch_bounds__(512) void scan3(int NBa)
{
    __shared__ int ws[16];
    const int b = blockIdx.x;
    int* cnt        = (b < NBa) ? g_cnt_aa : g_cnt_as;
    int* off        = (b < NBa) ? g_off_aa : g_off_as;
    const int* bsum = (b < NBa) ? g_bsum_aa : g_bsum_as;
    const int lb    = (b < NBa) ? b : b - NBa;
    const int N     = (b < NBa) ? NA : NS;
    const int NB    = (b < NBa) ? NB_AA : NB_AS;

    const int t = threadIdx.x;
    const int wid = t >> 5, lane = t & 31;
    const int base = lb * SCAN_ELEMS + t * 4;
    int4 v = make_int4(0, 0, 0, 0);
    if (base + 3 < N) v = *(const int4*)(cnt + base);
    else {
        if (base + 0 < N) v.x = cnt[base + 0];
        if (base + 1 < N) v.y = cnt[base + 1];
        if (base + 2 < N) v.z = cnt[base + 2];
    }
    int s = v.x + v.y + v.z + v.w;
    int inc = s;
#pragma unroll
    for (int o = 1; o < 32; o <<= 1) {
        int u = __shfl_up_sync(0xffffffffu, inc, o);
        if (lane >= o) inc += u;
    }
    if (lane == 31) ws[wid] = inc;
    __syncthreads();
    if (t < 32) {
        int x = (t < 16) ? ws[t] : 0;
#pragma unroll
        for (int o = 1; o < 32; o <<= 1) {
            int u = __shfl_up_sync(0xffffffffu, x, o);
            if (t >= o) x += u;
        }
        if (t < 16) ws[t] = x;
    }
    __syncthreads();
    int wbase = (wid == 0) ? 0 : ws[wid - 1];
    int tbase = bsum[lb] + wbase + (inc - s);
    int4 p = make_int4(tbase, tbase + v.x, tbase + v.x + v.y, tbase + v.x + v.y + v.z);
    if (base + 3 < N) {
        *(int4*)(off + base) = p;
        *(int4*)(cnt + base) = make_int4(0, 0, 0, 0);
    } else {
        if (base + 0 < N) { off[base + 0] = p.x; cnt[base + 0] = 0; }
        if (base + 1 < N) { off[base + 1] = p.y; cnt[base + 1] = 0; }
        if (base + 2 < N) { off[base + 2] = p.z; cnt[base + 2] = 0; }
    }
    if (lb == 0 && t == 0) off[N] = bsum[NB];
}

__global__ void csr_fill2(const int* __restrict__ dst_aa, const int* __restrict__ src_aa,
                          const int* __restrict__ dst_as, const int* __restrict__ src_as)
{
    int e = blockIdx.x * 256 + threadIdx.x;
    if (e < EAA) {
        int d = dst_aa[e];
        int pos = g_off_aa[d] + atomicAdd(&g_cnt_aa[d], 1);
        g_csr_aa[pos] = make_int2(e, src_aa[e]);
    }
    if (e < EAS) {
        int d = dst_as[e];
        int pos = g_off_as[d] + atomicAdd(&g_cnt_as[d], 1);
        g_csr_as[pos] = make_int2(e, src_as[e]);
    }
}

// ---------------- per-dst GATv2 aggregation (R12: 4-wide + scalar tail) ----------------
__device__ __forceinline__ void process_dst(
    int d, const int2* __restrict__ csr, const int* __restrict__ off,
    const float* __restrict__ eattr, const float4* Wreg,
    float4 a4, float4 bv,
    const float4* __restrict__ xl4, const float* __restrict__ xr,
    float* __restrict__ out, int relu, int lane)
{
    const float4 xrv = ((const float4*)xr)[(size_t)d * 32 + lane];
    float4 acc = make_float4(0.f, 0.f, 0.f, 0.f);
    float den = 0.0f;

    const int beg = off[d], end = off[d + 1];
    int i = beg;
    for (; i + 4 <= end; i += 4) {
        int2 es[4];
        float4 x[4], eaAv[4], eaBv[4];
#pragma unroll
        for (int j = 0; j < 4; j++) es[j] = csr[i + j];
#pragma unroll
        for (int j = 0; j < 4; j++) x[j] = xl4[(size_t)es[j].y * 32 + lane];
#pragma unroll
        for (int j = 0; j < 4; j++) {
            const float4* ea = (const float4*)(eattr + (size_t)es[j].x * ED);
            eaAv[j] = ea[0]; eaBv[j] = ea[1];
        }
        float lg[4];
#pragma unroll
        for (int j = 0; j < 4; j++) {
            float4 m = make_float4(x[j].x + xrv.x, x[j].y + xrv.y,
                                   x[j].z + xrv.z, x[j].w + xrv.w);
            float ja[ED] = {eaAv[j].x, eaAv[j].y, eaAv[j].z, eaAv[j].w,
                            eaBv[j].x, eaBv[j].y, eaBv[j].z, eaBv[j].w};
#pragma unroll
            for (int q = 0; q < ED; q++) {
                float4 wv = Wreg[q];
                m.x = fmaf(ja[q], wv.x, m.x); m.y = fmaf(ja[q], wv.y, m.y);
                m.z = fmaf(ja[q], wv.z, m.z); m.w = fmaf(ja[q], wv.w, m.w);
            }
            lg[j] = lkrelu(m.x) * a4.x + lkrelu(m.y) * a4.y +
                    lkrelu(m.z) * a4.z + lkrelu(m.w) * a4.w;
        }
#pragma unroll
        for (int o = 16; o; o >>= 1) {
#pragma unroll
            for (int j = 0; j < 4; j++)
                lg[j] += __shfl_xor_sync(0xffffffffu, lg[j], o);
        }
#pragma unroll
        for (int j = 0; j < 4; j++) {
            const float ee = __expf(lg[j]);
            den += ee;
            acc.x = fmaf(ee, x[j].x, acc.x); acc.y = fmaf(ee, x[j].y, acc.y);
            acc.z = fmaf(ee, x[j].z, acc.z); acc.w = fmaf(ee, x[j].w, acc.w);
        }
    }
    for (; i < end; i++) {
        const int2 es = csr[i];
        const float4 x0 = xl4[(size_t)es.y * 32 + lane];
        const float4* ea = (const float4*)(eattr + (size_t)es.x * ED);
        float4 eaAv = ea[0], eaBv = ea[1];
        float4 m = make_float4(x0.x + xrv.x, x0.y + xrv.y, x0.z + xrv.z, x0.w + xrv.w);
        float ja[ED] = {eaAv.x, eaAv.y, eaAv.z, eaAv.w, eaBv.x, eaBv.y, eaBv.z, eaBv.w};
#pragma unroll
        for (int q = 0; q < ED; q++) {
            float4 wv = Wreg[q];
            m.x = fmaf(ja[q], wv.x, m.x); m.y = fmaf(ja[q], wv.y, m.y);
            m.z = fmaf(ja[q], wv.z, m.z); m.w = fmaf(ja[q], wv.w, m.w);
        }
        float lg = lkrelu(m.x) * a4.x + lkrelu(m.y) * a4.y +
                   lkrelu(m.z) * a4.z + lkrelu(m.w) * a4.w;
#pragma unroll
        for (int o = 16; o; o >>= 1) lg += __shfl_xor_sync(0xffffffffu, lg, o);
        const float ee = __expf(lg);
        den += ee;
        acc.x = fmaf(ee, x0.x, acc.x); acc.y = fmaf(ee, x0.y, acc.y);
        acc.z = fmaf(ee, x0.z, acc.z); acc.w = fmaf(ee, x0.w, acc.w);
    }

    const float inv = 1.0f / fmaxf(den, 1e-16f);
    float4 v = make_float4(acc.x * inv + bv.x, acc.y * inv + bv.y,
                           acc.z * inv + bv.z, acc.w * inv + bv.w);
    if (relu) {
        v.x = fmaxf(v.x, 0.f); v.y = fmaxf(v.y, 0.f);
        v.z = fmaxf(v.z, 0.f); v.w = fmaxf(v.w, 0.f);
    }
    float sq = v.x * v.x + v.y * v.y + v.z * v.z + v.w * v.w;
#pragma unroll
    for (int o = 16; o; o >>= 1) sq += __shfl_xor_sync(0xffffffffu, sq, o);
    const float s = 1.0f / fmaxf(sqrtf(sq), 1e-12f);
    ((float4*)out)[(size_t)d * 32 + lane] =
        make_float4(v.x * s, v.y * s, v.z * s, v.w * s);
}

// ---------------- persistent work-stealing aggregation (128-thread blocks) ----------------
__global__ __launch_bounds__(128) void gat_persist(
    const float* __restrict__ eaA, const float* __restrict__ WeA,
    const float* __restrict__ attA, const float* __restrict__ xlA,
    const float* __restrict__ xrA, const float* __restrict__ bA,
    float* __restrict__ outA,
    const float* __restrict__ eaS, const float* __restrict__ WeS,
    const float* __restrict__ attS, const float* __restrict__ xlS,
    const float* __restrict__ xrS, const float* __restrict__ bS,
    float* __restrict__ outS,
    int relu, int* __restrict__ ctrA, int* __restrict__ ctrS)
{
    const int lane = threadIdx.x & 31;
    float4 Wreg[ED];

    // ---- style phase (degree ~50, long tasks first) ----
    {
#pragma unroll
        for (int q = 0; q < ED; q++) Wreg[q] = ((const float4*)WeS)[q * 32 + lane];
        const float4 a4 = ((const float4*)attS)[lane];
        const float4 bv = ((const float4*)bS)[lane];
        for (;;) {
            int i = 0;
            if (lane == 0) i = atomicAdd(ctrS, 2);
            i = __shfl_sync(0xffffffffu, i, 0);
            if (i >= NS) break;
            const int e = min(i + 2, NS);
            for (int d = i; d < e; d++)
                process_dst(d, g_csr_as, g_off_as, eaS, Wreg, a4, bv,
                            (const float4*)xlS, xrS, outS, relu, lane);
        }
    }
    // ---- artist phase (degree ~10) ----
    {
#pragma unroll
        for (int q = 0; q < ED; q++) Wreg[q] = ((const float4*)WeA)[q * 32 + lane];
        const float4 a4 = ((const float4*)attA)[lane];
        const float4 bv = ((const float4*)bA)[lane];
        for (;;) {
            int i = 0;
            if (lane == 0) i = atomicAdd(ctrA, 8);
            i = __shfl_sync(0xffffffffu, i, 0);
            if (i >= NA) break;
            const int e = min(i + 8, NA);
            for (int d = i; d < e; d++)
                process_dst(d, g_csr_aa, g_off_aa, eaA, Wreg, a4, bv,
                            (const float4*)xlA, xrA, outA, relu, lane);
        }
    }
}

// ---------------- host ----------------
extern "C" void kernel_launch(void* const* d_in, const int* in_sizes, int n_in,
                              void* d_out, int out_size)
{
    const float* x_a   = (const float*)d_in[0];
    const float* x_s   = (const float*)d_in[1];
    const int* src_aa  = (const int*)d_in[2];
    const int* dst_aa  = (const int*)d_in[3];
    const float* ea_aa = (const float*)d_in[4];
    const int* src_as  = (const int*)d_in[5];
    const int* dst_as  = (const int*)d_in[6];
    const float* ea_as = (const float*)d_in[7];

    const float* Wl0_aa  = (const float*)d_in[8];
    const float* Wr0_aa  = (const float*)d_in[9];
    const float* att0_aa = (const float*)d_in[10];
    const float* We0_aa  = (const float*)d_in[11];
    const float* b0_aa   = (const float*)d_in[12];
    const float* Wl0_as  = (const float*)d_in[13];
    const float* Wr0_as  = (const float*)d_in[14];
    const float* att0_as = (const float*)d_in[15];
    const float* We0_as  = (const float*)d_in[16];
    const float* b0_as   = (const float*)d_in[17];
    const float* Wl_aa   = (const float*)d_in[18];
    const float* Wr_aa   = (const float*)d_in[19];
    const float* att_aa  = (const float*)d_in[20];
    const float* We_aa   = (const float*)d_in[21];
    const float* b_aa    = (const float*)d_in[22];
    const float* Wl_as   = (const float*)d_in[23];
    const float* Wr_as   = (const float*)d_in[24];
    const float* att_as  = (const float*)d_in[25];
    const float* We_as   = (const float*)d_in[26];
    const float* b_as    = (const float*)d_in[27];

    float *ha, *hs, *xl_aa, *xr_aa, *xl_as, *xr_as;
    int *wctrA, *wctrS;
    cudaGetSymbolAddress((void**)&ha,    g_ha);
    cudaGetSymbolAddress((void**)&hs,    g_hs);
    cudaGetSymbolAddress((void**)&xl_aa, g_xl_aa);
    cudaGetSymbolAddress((void**)&xr_aa, g_xr_aa);
    cudaGetSymbolAddress((void**)&xl_as, g_xl_as);
    cudaGetSymbolAddress((void**)&xr_as, g_xr_as);
    cudaGetSymbolAddress((void**)&wctrA, g_wctrA);
    cudaGetSymbolAddress((void**)&wctrS, g_wctrS);

    cudaFuncSetAttribute(gemm_dual, cudaFuncAttributeMaxDynamicSharedMemorySize, SM_GEMM_BYTES);

    const int GA = (NA + 127) / 128;    // 391
    const int GS = (NS + 127) / 128;    // 40
    const int PERSIST_BLOCKS = 1216;    // 128-thread blocks (~8/SM, warp granularity)

    zero_cnt<<<(NA + 255) / 256, 256>>>();                                 // 0
    hist2<<<(EAA + 255) / 256, 256>>>(dst_aa, dst_as);                     // 1
    scan1<<<NB_AA + NB_AS, 512>>>(NB_AA);                                  // 2
    gemm_dual<<<GA + GS, 1024, SM_GEMM_BYTES>>>(                           // 3
        x_a, Wl0_aa, Wr0_aa, Wl0_as, xl_aa, xr_aa, xl_as, NA, 7, GA,
        x_s, Wr0_as, xr_as, NS, 6);
    scan2<<<2, 32>>>();                                                    // 4
    scan3<<<NB_AA + NB_AS, 512>>>(NB_AA);                                  // 5
    csr_fill2<<<(EAA + 255) / 256, 256>>>(dst_aa, src_aa, dst_as, src_as); // 6

    for (int layer = 0; layer < 3; layer++) {
        const float *patt_aa, *pWe_aa, *pb_aa, *patt_as, *pWe_as, *pb_as;
        if (layer > 0) {
            int j = layer - 1;
            const float* pWl_aa = Wl_aa + (size_t)j * C * C;
            const float* pWr_aa = Wr_aa + (size_t)j * C * C;
            const float* pWl_as = Wl_as + (size_t)j * C * C;
            const float* pWr_as = Wr_as + (size_t)j * C * C;
            gemm_dual<<<GA + GS, 1024, SM_GEMM_BYTES>>>(
                ha, pWl_aa, pWr_aa, pWl_as, xl_aa, xr_aa, xl_as, NA, 7, GA,
                hs, pWr_as, xr_as, NS, 7);
            patt_aa = att_aa + (size_t)j * C;  pWe_aa = We_aa + (size_t)j * ED * C;
            pb_aa = b_aa + (size_t)j * C;
            patt_as = att_as + (size_t)j * C;  pWe_as = We_as + (size_t)j * ED * C;
            pb_as = b_as + (size_t)j * C;
        } else {
            patt_aa = att0_aa; pWe_aa = We0_aa; pb_aa = b0_aa;
            patt_as = att0_as; pWe_as = We0_as; pb_as = b0_as;
        }

        int relu = (layer < 2) ? 1 : 0;
        float* outA = (layer == 2) ? (float*)d_out : ha;
        float* outS = (layer == 2) ? ((float*)d_out + (size_t)NA * C) : hs;

        gat_persist<<<PERSIST_BLOCKS, 128>>>(
            ea_aa, pWe_aa, patt_aa, xl_aa, xr_aa, pb_aa, outA,
            ea_as, pWe_as, patt_as, xl_as, xr_as, pb_as, outS,
            relu, wctrA + layer, wctrS + layer);
    }
}

// round 15
// speedup vs baseline: 1.2047x; 1.0106x over previous
#include <cuda_runtime.h>
#include <cuda_bf16.h>
#include <math.h>
#include <stdint.h>

#define NA   50000
#define NS   5000
#define EAA  500000
#define EAS  250000
#define C    128
#define ED   8

#define SCAN_ELEMS 2048
#define NB_AA ((NA + SCAN_ELEMS - 1) / SCAN_ELEMS)
#define NB_AS ((NS + SCAN_ELEMS - 1) / SCAN_ELEMS)

// ---------------- device scratch ----------------
__device__ float g_ha[NA * C];
__device__ float g_hs[NS * C];
__device__ float g_xl_aa[NA * C];
__device__ float g_xr_aa[NA * C];
__device__ float g_xl_as[NA * C];
__device__ float g_xr_as[NS * C];
__device__ int  g_cnt_aa[NA];
__device__ int  g_off_aa[NA + 4];
__device__ int2 g_csr_aa[EAA];
__device__ int  g_cnt_as[NS];
__device__ int  g_off_as[NS + 4];
__device__ int2 g_csr_as[EAS];
__device__ int  g_bsum_aa[NB_AA + 1];
__device__ int  g_bsum_as[NB_AS + 1];
__device__ int  g_wctrA[3];
__device__ int  g_wctrS[3];

// ---------------- helpers ----------------
__device__ __forceinline__ float lkrelu(float x) { return x > 0.0f ? x : 0.2f * x; }

__device__ __forceinline__ uint32_t bf16_hi_bits(float v, float& hf) {
    __nv_bfloat16 h = __float2bfloat16(v);
    hf = __bfloat162float(h);
    uint16_t b = *(uint16_t*)&h;
    return (uint32_t)b;
}

__device__ __forceinline__ void mma16(float* c, const uint32_t* a, const uint32_t* b) {
    asm volatile(
        "mma.sync.aligned.m16n8k16.row.col.f32.bf16.bf16.f32 "
        "{%0,%1,%2,%3}, {%4,%5,%6,%7}, {%8,%9}, {%0,%1,%2,%3};"
        : "+f"(c[0]), "+f"(c[1]), "+f"(c[2]), "+f"(c[3])
        : "r"(a[0]), "r"(a[1]), "r"(a[2]), "r"(a[3]),
          "r"(b[0]), "r"(b[1]));
}

// ---------------- BF16 GEMM: 1024 thr, m16n32 warp tile, 3xBF16, double-buffered W ----
// smem: A 64KB + 2 x (Whi+Wlo 66KB) = 197KB
#define SM_GEMM_BYTES (65536 + 2 * 67584)

__device__ __forceinline__ void stage_w_bf16(const float* __restrict__ W,
                                             uint32_t* __restrict__ sWhi,
                                             uint32_t* __restrict__ sWlo,
                                             int K, int tid)
{
    const int total2 = K << 6;            // (K/2)*128 pairs
    for (int idx = tid; idx < total2; idx += 1024) {
        int kp = idx >> 7, n = idx & 127;
        int k = kp << 1;
        float v0 = W[((size_t)k << 7) + n];
        float v1 = W[((size_t)(k + 1) << 7) + n];
        float h0f, h1f;
        uint32_t h0 = bf16_hi_bits(v0, h0f);
        uint32_t h1 = bf16_hi_bits(v1, h1f);
        float l0f, l1f;
        uint32_t l0 = bf16_hi_bits(v0 - h0f, l0f);
        uint32_t l1 = bf16_hi_bits(v1 - h1f, l1f);
        int u32i = (((k >> 4) * 4 + ((k >> 1) & 3)) * 132 + n) * 2 + ((k >> 3) & 1);
        sWhi[u32i] = h0 | (h1 << 16);
        sWlo[u32i] = l0 | (l1 << 16);
    }
}

__global__ __launch_bounds__(1024, 1) void gemm_dual(
    const float* __restrict__ XA,
    const float* __restrict__ Wa0, const float* __restrict__ Wa1, const float* __restrict__ Wa2,
    float* __restrict__ Ya0, float* __restrict__ Ya1, float* __restrict__ Ya2,
    int NrowsA, int kshiftA, int gridA,
    const float* __restrict__ XS, const float* __restrict__ Ws,
    float* __restrict__ Ys, int NrowsS, int kshiftS)
{
    extern __shared__ char smc[];

    const float *X, *W0, *W1, *W2;
    float *Y0, *Y1, *Y2;
    int Nrows, kshift, nW, rbase;
    if ((int)blockIdx.x < gridA) {
        X = XA; W0 = Wa0; W1 = Wa1; W2 = Wa2; Y0 = Ya0; Y1 = Ya1; Y2 = Ya2;
        Nrows = NrowsA; kshift = kshiftA; nW = 3; rbase = blockIdx.x * 128;
    } else {
        X = XS; W0 = Ws; W1 = Ws; W2 = Ws; Y0 = Ys; Y1 = Ys; Y2 = Ys;
        Nrows = NrowsS; kshift = kshiftS; nW = 1; rbase = (blockIdx.x - gridA) * 128;
    }

    const int K = 1 << kshift;
    const int ksteps = K >> 4;
    const int WSZ = ksteps * 4 * 132 * 2;             // u32 per W half-buffer
    uint32_t* sAhi = (uint32_t*)smc;                  // 128*K/2 u32 (bf16 pairs)
    uint32_t* sAlo = sAhi + 64 * K;
    uint32_t* wbuf = (uint32_t*)(smc + 128 * K * 4);  // [hi0, lo0, hi1, lo1]

    const int tid = threadIdx.x;
    const int lane = tid & 31;
    const int warp = tid >> 5;
    const int gid = lane >> 2;
    const int tg  = lane & 3;
    const int wm = warp >> 2;
    const int wn = warp & 3;

    // ---- stage A hi/lo bf16 pairs ----
    {
        const int total2 = 64 << kshift;
        const int kpmask = (K >> 1) - 1;
        const int kps = kshift - 1;
        for (int idx = tid; idx < total2; idx += 1024) {
            int row = idx >> kps, kp = idx & kpmask;
            int k = kp << 1;
            float2 v = make_float2(0.f, 0.f);
            if (rbase + row < Nrows)
                v = *(const float2*)&X[((size_t)(rbase + row) << kshift) + k];
            float h0f, h1f;
            uint32_t h0 = bf16_hi_bits(v.x, h0f);
            uint32_t h1 = bf16_hi_bits(v.y, h1f);
            float l0f, l1f;
            uint32_t l0 = bf16_hi_bits(v.x - h0f, l0f);
            uint32_t l1 = bf16_hi_bits(v.y - h1f, l1f);
            int frag = (row >> 4) * ksteps + (k >> 4);
            int alane = (row & 7) * 4 + ((k >> 1) & 3);
            int reg = ((row >> 3) & 1) + 2 * ((k >> 3) & 1);
            int u32i = frag * 128 + alane * 4 + reg;
            sAhi[u32i] = h0 | (h1 << 16);
            sAlo[u32i] = l0 | (l1 << 16);
        }
    }
    // ---- stage W0 into buffer 0 (no sync needed between A and W0 staging) ----
    stage_w_bf16(W0, wbuf, wbuf + WSZ, K, tid);
    __syncthreads();

    const uint4* A4hi = (const uint4*)sAhi;
    const uint4* A4lo = (const uint4*)sAlo;

    for (int wi = 0; wi < nW; wi++) {
        const int cur = wi & 1;
        const uint2* Whi2 = (const uint2*)(wbuf + cur * 2 * WSZ);
        const uint2* Wlo2 = (const uint2*)(wbuf + cur * 2 * WSZ + WSZ);

        float acc[4][4];
#pragma unroll
        for (int in = 0; in < 4; in++)
#pragma unroll
            for (int j = 0; j < 4; j++) acc[in][j] = 0.0f;

        for (int ks = 0; ks < ksteps; ks++) {
            const int wb = (ks * 4 + tg) * 132 + wn * 32 + gid;
            uint2 bhi[4], blo[4];
#pragma unroll
            for (int in = 0; in < 4; in++) {
                bhi[in] = Whi2[wb + in * 8];
                blo[in] = Wlo2[wb + in * 8];
            }
            const int fidx = (wm * ksteps + ks) * 32 + lane;
            uint4 ah = A4hi[fidx];
            uint4 al = A4lo[fidx];
#pragma unroll
            for (int in = 0; in < 4; in++)
                mma16(acc[in], &ah.x, &bhi[in].x);
#pragma unroll
            for (int in = 0; in < 4; in++)
                mma16(acc[in], &al.x, &bhi[in].x);
#pragma unroll
            for (int in = 0; in < 4; in++)
                mma16(acc[in], &ah.x, &blo[in].x);
        }

        // ---- write Y ----
        float* Y = (wi == 0) ? Y0 : (wi == 1) ? Y1 : Y2;
        {
            int r0 = rbase + wm * 16 + gid;
#pragma unroll
            for (int in = 0; in < 4; in++) {
                int col = wn * 32 + in * 8 + tg * 2;
                if (r0 < Nrows)
                    *(float2*)&Y[((size_t)r0 << 7) + col] =
                        make_float2(acc[in][0], acc[in][1]);
                if (r0 + 8 < Nrows)
                    *(float2*)&Y[((size_t)(r0 + 8) << 7) + col] =
                        make_float2(acc[in][2], acc[in][3]);
            }
        }

        // ---- stage next W into the other buffer (overlaps other warps' k-loop) ----
        if (wi + 1 < nW) {
            const float* Wn = (wi + 1 == 1) ? W1 : W2;
            const int nxt = 1 - cur;
            stage_w_bf16(Wn, wbuf + nxt * 2 * WSZ, wbuf + nxt * 2 * WSZ + WSZ, K, tid);
        }
        __syncthreads();
    }
}

// ---------------- CSR build ----------------
__global__ void zero_cnt()
{
    int i = blockIdx.x * 256 + threadIdx.x;
    if (i < NA) g_cnt_aa[i] = 0;
    if (i < NS) g_cnt_as[i] = 0;
    if (i < 3) { g_wctrA[i] = 0; g_wctrS[i] = 0; }
}

__global__ void hist2(const int* __restrict__ dst_aa, const int* __restrict__ dst_as)
{
    int e = blockIdx.x * 256 + threadIdx.x;
    if (e < EAA) atomicAdd(&g_cnt_aa[dst_aa[e]], 1);
    if (e < EAS) atomicAdd(&g_cnt_as[dst_as[e]], 1);
}

__global__ __launch_bounds__(512) void scan1(int NBa)
{
    __shared__ int ws[16];
    const int b = blockIdx.x;
    const int* cnt = (b < NBa) ? g_cnt_aa : g_cnt_as;
    int* bsum      = (b < NBa) ? g_bsum_aa : g_bsum_as;
    const int lb   = (b < NBa) ? b : b - NBa;
    const int N    = (b < NBa) ? NA : NS;

    const int t = threadIdx.x;
    const int base = lb * SCAN_ELEMS + t * 4;
    int4 v = make_int4(0, 0, 0, 0);
    if (base + 3 < N) v = *(const int4*)(cnt + base);
    else {
        if (base + 0 < N) v.x = cnt[base + 0];
        if (base + 1 < N) v.y = cnt[base + 1];
        if (base + 2 < N) v.z = cnt[base + 2];
    }
    int s = v.x + v.y + v.z + v.w;
#pragma unroll
    for (int o = 16; o; o >>= 1) s += __shfl_xor_sync(0xffffffffu, s, o);
    if ((t & 31) == 0) ws[t >> 5] = s;
    __syncthreads();
    if (t < 32) {
        int x = (t < 16) ? ws[t] : 0;
#pragma unroll
        for (int o = 16; o; o >>= 1) x += __shfl_xor_sync(0xffffffffu, x, o);
        if (t == 0) bsum[lb] = x;
    }
}

__global__ void scan2()
{
    if (threadIdx.x != 0) return;
    if (blockIdx.x == 0) {
        int run = 0;
        for (int i = 0; i < NB_AA; i++) { int t = g_bsum_aa[i]; g_bsum_aa[i] = run; run += t; }
        g_bsum_aa[NB_AA] = run;
    } else {
        int run = 0;
        for (int i = 0; i < NB_AS; i++) { int t = g_bsum_as[i]; g_bsum_as[i] = run; run += t; }
        g_bsum_as[NB_AS] = run;
    }
}

__global__ __launch_bounds__(512) void scan3(int NBa)
{
    __shared__ int ws[16];
    const int b = blockIdx.x;
    int* cnt        = (b < NBa) ? g_cnt_aa : g_cnt_as;
    int* off        = (b < NBa) ? g_off_aa : g_off_as;
    const int* bsum = (b < NBa) ? g_bsum_aa : g_bsum_as;
    const int lb    = (b < NBa) ? b : b - NBa;
    const int N     = (b < NBa) ? NA : NS;
    const int NB    = (b < NBa) ? NB_AA : NB_AS;

    const int t = threadIdx.x;
    const int wid = t >> 5, lane = t & 31;
    const int base = lb * SCAN_ELEMS + t * 4;
    int4 v = make_int4(0, 0, 0, 0);
    if (base + 3 < N) v = *(const int4*)(cnt + base);
    else {
        if (base + 0 < N) v.x = cnt[base + 0];
        if (base + 1 < N) v.y = cnt[base + 1];
        if (base + 2 < N) v.z = cnt[base + 2];
    }
    int s = v.x + v.y + v.z + v.w;
    int inc = s;
#pragma unroll
    for (int o = 1; o < 32; o <<= 1) {
        int u = __shfl_up_sync(0xffffffffu, inc, o);
        if (lane >= o) inc += u;
    }
    if (lane == 31) ws[wid] = inc;
    __syncthreads();
    if (t < 32) {
        int x = (t < 16) ? ws[t] : 0;
#pragma unroll
        for (int o = 1; o < 32; o <<= 1) {
            int u = __shfl_up_sync(0xffffffffu, x, o);
            if (t >= o) x += u;
        }
        if (t < 16) ws[t] = x;
    }
    __syncthreads();
    int wbase = (wid == 0) ? 0 : ws[wid - 1];
    int tbase = bsum[lb] + wbase + (inc - s);
    int4 p = make_int4(tbase, tbase + v.x, tbase + v.x + v.y, tbase + v.x + v.y + v.z);
    if (base + 3 < N) {
        *(int4*)(off + base) = p;
        *(int4*)(cnt + base) = make_int4(0, 0, 0, 0);
    } else {
        if (base + 0 < N) { off[base + 0] = p.x; cnt[base + 0] = 0; }
        if (base + 1 < N) { off[base + 1] = p.y; cnt[base + 1] = 0; }
        if (base + 2 < N) { off[base + 2] = p.z; cnt[base + 2] = 0; }
    }
    if (lb == 0 && t == 0) off[N] = bsum[NB];
}

__global__ void csr_fill2(const int* __restrict__ dst_aa, const int* __restrict__ src_aa,
                          const int* __restrict__ dst_as, const int* __restrict__ src_as)
{
    int e = blockIdx.x * 256 + threadIdx.x;
    if (e < EAA) {
        int d = dst_aa[e];
        int pos = g_off_aa[d] + atomicAdd(&g_cnt_aa[d], 1);
        g_csr_aa[pos] = make_int2(e, src_aa[e]);
    }
    if (e < EAS) {
        int d = dst_as[e];
        int pos = g_off_as[d] + atomicAdd(&g_cnt_as[d], 1);
        g_csr_as[pos] = make_int2(e, src_as[e]);
    }
}

// ---------------- per-dst GATv2 aggregation (4-wide + scalar tail) ----------------
__device__ __forceinline__ void process_dst(
    int d, const int2* __restrict__ csr, const int* __restrict__ off,
    const float* __restrict__ eattr, const float4* Wreg,
    float4 a4, float4 bv,
    const float4* __restrict__ xl4, const float* __restrict__ xr,
    float* __restrict__ out, int relu, int lane)
{
    const float4 xrv = ((const float4*)xr)[(size_t)d * 32 + lane];
    float4 acc = make_float4(0.f, 0.f, 0.f, 0.f);
    float den = 0.0f;

    const int beg = off[d], end = off[d + 1];
    int i = beg;
    for (; i + 4 <= end; i += 4) {
        int2 es[4];
        float4 x[4], eaAv[4], eaBv[4];
#pragma unroll
        for (int j = 0; j < 4; j++) es[j] = csr[i + j];
#pragma unroll
        for (int j = 0; j < 4; j++) x[j] = xl4[(size_t)es[j].y * 32 + lane];
#pragma unroll
        for (int j = 0; j < 4; j++) {
            const float4* ea = (const float4*)(eattr + (size_t)es[j].x * ED);
            eaAv[j] = ea[0]; eaBv[j] = ea[1];
        }
        float lg[4];
#pragma unroll
        for (int j = 0; j < 4; j++) {
            float4 m = make_float4(x[j].x + xrv.x, x[j].y + xrv.y,
                                   x[j].z + xrv.z, x[j].w + xrv.w);
            float ja[ED] = {eaAv[j].x, eaAv[j].y, eaAv[j].z, eaAv[j].w,
                            eaBv[j].x, eaBv[j].y, eaBv[j].z, eaBv[j].w};
#pragma unroll
            for (int q = 0; q < ED; q++) {
                float4 wv = Wreg[q];
                m.x = fmaf(ja[q], wv.x, m.x); m.y = fmaf(ja[q], wv.y, m.y);
                m.z = fmaf(ja[q], wv.z, m.z); m.w = fmaf(ja[q], wv.w, m.w);
            }
            lg[j] = lkrelu(m.x) * a4.x + lkrelu(m.y) * a4.y +
                    lkrelu(m.z) * a4.z + lkrelu(m.w) * a4.w;
        }
#pragma unroll
        for (int o = 16; o; o >>= 1) {
#pragma unroll
            for (int j = 0; j < 4; j++)
                lg[j] += __shfl_xor_sync(0xffffffffu, lg[j], o);
        }
#pragma unroll
        for (int j = 0; j < 4; j++) {
            const float ee = __expf(lg[j]);
            den += ee;
            acc.x = fmaf(ee, x[j].x, acc.x); acc.y = fmaf(ee, x[j].y, acc.y);
            acc.z = fmaf(ee, x[j].z, acc.z); acc.w = fmaf(ee, x[j].w, acc.w);
        }
    }
    for (; i < end; i++) {
        const int2 es = csr[i];
        const float4 x0 = xl4[(size_t)es.y * 32 + lane];
        const float4* ea = (const float4*)(eattr + (size_t)es.x * ED);
        float4 eaAv = ea[0], eaBv = ea[1];
        float4 m = make_float4(x0.x + xrv.x, x0.y + xrv.y, x0.z + xrv.z, x0.w + xrv.w);
        float ja[ED] = {eaAv.x, eaAv.y, eaAv.z, eaAv.w, eaBv.x, eaBv.y, eaBv.z, eaBv.w};
#pragma unroll
        for (int q = 0; q < ED; q++) {
            float4 wv = Wreg[q];
            m.x = fmaf(ja[q], wv.x, m.x); m.y = fmaf(ja[q], wv.y, m.y);
            m.z = fmaf(ja[q], wv.z, m.z); m.w = fmaf(ja[q], wv.w, m.w);
        }
        float lg = lkrelu(m.x) * a4.x + lkrelu(m.y) * a4.y +
                   lkrelu(m.z) * a4.z + lkrelu(m.w) * a4.w;
#pragma unroll
        for (int o = 16; o; o >>= 1) lg += __shfl_xor_sync(0xffffffffu, lg, o);
        const float ee = __expf(lg);
        den += ee;
        acc.x = fmaf(ee, x0.x, acc.x); acc.y = fmaf(ee, x0.y, acc.y);
        acc.z = fmaf(ee, x0.z, acc.z); acc.w = fmaf(ee, x0.w, acc.w);
    }

    const float inv = 1.0f / fmaxf(den, 1e-16f);
    float4 v = make_float4(acc.x * inv + bv.x, acc.y * inv + bv.y,
                           acc.z * inv + bv.z, acc.w * inv + bv.w);
    if (relu) {
        v.x = fmaxf(v.x, 0.f); v.y = fmaxf(v.y, 0.f);
        v.z = fmaxf(v.z, 0.f); v.w = fmaxf(v.w, 0.f);
    }
    float sq = v.x * v.x + v.y * v.y + v.z * v.z + v.w * v.w;
#pragma unroll
    for (int o = 16; o; o >>= 1) sq += __shfl_xor_sync(0xffffffffu, sq, o);
    const float s = 1.0f / fmaxf(sqrtf(sq), 1e-12f);
    ((float4*)out)[(size_t)d * 32 + lane] =
        make_float4(v.x * s, v.y * s, v.z * s, v.w * s);
}

// ---------------- persistent work-stealing aggregation (128-thread blocks) ----------------
__global__ __launch_bounds__(128) void gat_persist(
    const float* __restrict__ eaA, const float* __restrict__ WeA,
    const float* __restrict__ attA, const float* __restrict__ xlA,
    const float* __restrict__ xrA, const float* __restrict__ bA,
    float* __restrict__ outA,
    const float* __restrict__ eaS, const float* __restrict__ WeS,
    const float* __restrict__ attS, const float* __restrict__ xlS,
    const float* __restrict__ xrS, const float* __restrict__ bS,
    float* __restrict__ outS,
    int relu, int* __restrict__ ctrA, int* __restrict__ ctrS)
{
    const int lane = threadIdx.x & 31;
    float4 Wreg[ED];

    // ---- style phase (degree ~50, long tasks first) ----
    {
#pragma unroll
        for (int q = 0; q < ED; q++) Wreg[q] = ((const float4*)WeS)[q * 32 + lane];
        const float4 a4 = ((const float4*)attS)[lane];
        const float4 bv = ((const float4*)bS)[lane];
        for (;;) {
            int i = 0;
            if (lane == 0) i = atomicAdd(ctrS, 2);
            i = __shfl_sync(0xffffffffu, i, 0);
            if (i >= NS) break;
            const int e = min(i + 2, NS);
            for (int d = i; d < e; d++)
                process_dst(d, g_csr_as, g_off_as, eaS, Wreg, a4, bv,
                            (const float4*)xlS, xrS, outS, relu, lane);
        }
    }
    // ---- artist phase (degree ~10) ----
    {
#pragma unroll
        for (int q = 0; q < ED; q++) Wreg[q] = ((const float4*)WeA)[q * 32 + lane];
        const float4 a4 = ((const float4*)attA)[lane];
        const float4 bv = ((const float4*)bA)[lane];
        for (;;) {
            int i = 0;
            if (lane == 0) i = atomicAdd(ctrA, 8);
            i = __shfl_sync(0xffffffffu, i, 0);
            if (i >= NA) break;
            const int e = min(i + 8, NA);
            for (int d = i; d < e; d++)
                process_dst(d, g_csr_aa, g_off_aa, eaA, Wreg, a4, bv,
                            (const float4*)xlA, xrA, outA, relu, lane);
        }
    }
}

// ---------------- host ----------------
extern "C" void kernel_launch(void* const* d_in, const int* in_sizes, int n_in,
                              void* d_out, int out_size)
{
    const float* x_a   = (const float*)d_in[0];
    const float* x_s   = (const float*)d_in[1];
    const int* src_aa  = (const int*)d_in[2];
    const int* dst_aa  = (const int*)d_in[3];
    const float* ea_aa = (const float*)d_in[4];
    const int* src_as  = (const int*)d_in[5];
    const int* dst_as  = (const int*)d_in[6];
    const float* ea_as = (const float*)d_in[7];

    const float* Wl0_aa  = (const float*)d_in[8];
    const float* Wr0_aa  = (const float*)d_in[9];
    const float* att0_aa = (const float*)d_in[10];
    const float* We0_aa  = (const float*)d_in[11];
    const float* b0_aa   = (const float*)d_in[12];
    const float* Wl0_as  = (const float*)d_in[13];
    const float* Wr0_as  = (const float*)d_in[14];
    const float* att0_as = (const float*)d_in[15];
    const float* We0_as  = (const float*)d_in[16];
    const float* b0_as   = (const float*)d_in[17];
    const float* Wl_aa   = (const float*)d_in[18];
    const float* Wr_aa   = (const float*)d_in[19];
    const float* att_aa  = (const float*)d_in[20];
    const float* We_aa   = (const float*)d_in[21];
    const float* b_aa    = (const float*)d_in[22];
    const float* Wl_as   = (const float*)d_in[23];
    const float* Wr_as   = (const float*)d_in[24];
    const float* att_as  = (const float*)d_in[25];
    const float* We_as   = (const float*)d_in[26];
    const float* b_as    = (const float*)d_in[27];

    float *ha, *hs, *xl_aa, *xr_aa, *xl_as, *xr_as;
    int *wctrA, *wctrS;
    cudaGetSymbolAddress((void**)&ha,    g_ha);
    cudaGetSymbolAddress((void**)&hs,    g_hs);
    cudaGetSymbolAddress((void**)&xl_aa, g_xl_aa);
    cudaGetSymbolAddress((void**)&xr_aa, g_xr_aa);
    cudaGetSymbolAddress((void**)&xl_as, g_xl_as);
    cudaGetSymbolAddress((void**)&xr_as, g_xr_as);
    cudaGetSymbolAddress((void**)&wctrA, g_wctrA);
    cudaGetSymbolAddress((void**)&wctrS, g_wctrS);

    cudaFuncSetAttribute(gemm_dual, cudaFuncAttributeMaxDynamicSharedMemorySize, SM_GEMM_BYTES);

    const int GA = (NA + 127) / 128;    // 391
    const int GS = (NS + 127) / 128;    // 40
    const int PERSIST_BLOCKS = 1216;

    zero_cnt<<<(NA + 255) / 256, 256>>>();                                 // 0
    hist2<<<(EAA + 255) / 256, 256>>>(dst_aa, dst_as);                     // 1
    scan1<<<NB_AA + NB_AS, 512>>>(NB_AA);                                  // 2
    gemm_dual<<<GA + GS, 1024, SM_GEMM_BYTES>>>(                           // 3
        x_a, Wl0_aa, Wr0_aa, Wl0_as, xl_aa, xr_aa, xl_as, NA, 7, GA,
        x_s, Wr0_as, xr_as, NS, 6);
    scan2<<<2, 32>>>();                                                    // 4
    scan3<<<NB_AA + NB_AS, 512>>>(NB_AA);                                  // 5
    csr_fill2<<<(EAA + 255) / 256, 256>>>(dst_aa, src_aa, dst_as, src_as); // 6

    for (int layer = 0; layer < 3; layer++) {
        const float *patt_aa, *pWe_aa, *pb_aa, *patt_as, *pWe_as, *pb_as;
        if (layer > 0) {
            int j = layer - 1;
            const float* pWl_aa = Wl_aa + (size_t)j * C * C;
            const float* pWr_aa = Wr_aa + (size_t)j * C * C;
            const float* pWl_as = Wl_as + (size_t)j * C * C;
            const float* pWr_as = Wr_as + (size_t)j * C * C;
            gemm_dual<<<GA + GS, 1024, SM_GEMM_BYTES>>>(
                ha, pWl_aa, pWr_aa, pWl_as, xl_aa, xr_aa, xl_as, NA, 7, GA,
                hs, pWr_as, xr_as, NS, 7);
            patt_aa = att_aa + (size_t)j * C;  pWe_aa = We_aa + (size_t)j * ED * C;
            pb_aa = b_aa + (size_t)j * C;
            patt_as = att_as + (size_t)j * C;  pWe_as = We_as + (size_t)j * ED * C;
            pb_as = b_as + (size_t)j * C;
        } else {
            patt_aa = att0_aa; pWe_aa = We0_aa; pb_aa = b0_aa;
            patt_as = att0_as; pWe_as = We0_as; pb_as = b0_as;
        }

        int relu = (layer < 2) ? 1 : 0;
        float* outA = (layer == 2) ? (float*)d_out : ha;
        float* outS = (layer == 2) ? ((float*)d_out + (size_t)NA * C) : hs;

        gat_persist<<<PERSIST_BLOCKS, 128>>>(
            ea_aa, pWe_aa, patt_aa, xl_aa, xr_aa, pb_aa, outA,
            ea_as, pWe_as, patt_as, xl_as, xr_as, pb_as, outS,
            relu, wctrA + layer, wctrS + layer);
    }
}